// round 5
// baseline (speedup 1.0000x reference)
#include <cuda_runtime.h>
#include <cuda_bf16.h>
#include <mma.h>
#include <math.h>
#include <stdint.h>

using namespace nvcuda;

// Problem constants: B=2, N=2048, C=1024, H=16, D=64
#define BATCH 2
#define SEQ   2048
#define CDIM  1024
#define HEADS 16
#define HDIM  64
#define ROWS  (BATCH*SEQ)          // 4096
#define FF    (4*CDIM)             // 4096

// ---------------- scratch (static device globals; no allocs allowed) ----------------
__device__ float g_h1[(size_t)ROWS*CDIM];   // LN1 out, later reused as h4 (fc2 out)
__device__ float g_q [(size_t)ROWS*CDIM];
__device__ float g_k [(size_t)ROWS*CDIM];
__device__ float g_v [(size_t)ROWS*CDIM];
__device__ float g_o [(size_t)ROWS*CDIM];   // attention out
__device__ float g_h2[(size_t)ROWS*CDIM];   // post-attn residual
__device__ float g_h3[(size_t)ROWS*CDIM];   // LN2 out, later reused as h5 (wout out)
__device__ float g_f1[(size_t)ROWS*FF];     // fc1/gelu out

// bf16 split buffers
__device__ __nv_bfloat16 g_ahi[(size_t)ROWS*FF];   // activation hi (max 4096x4096)
__device__ __nv_bfloat16 g_alo[(size_t)ROWS*FF];   // activation lo
__device__ __nv_bfloat16 g_wthi[(size_t)FF*CDIM];  // transposed weight hi (max 4096x1024)
__device__ __nv_bfloat16 g_wtlo[(size_t)FF*CDIM];  // transposed weight lo

// ===================== LayerNorm =====================
__inline__ __device__ float warp_sum(float v) {
    #pragma unroll
    for (int o = 16; o > 0; o >>= 1) v += __shfl_xor_sync(0xffffffffu, v, o);
    return v;
}

__global__ void ln_kernel(const float* __restrict__ x, const float* __restrict__ w,
                          const float* __restrict__ b, float* __restrict__ y) {
    int row = blockIdx.x;
    int tid = threadIdx.x;                  // 256 threads, 4 floats each
    const float4* xr = (const float4*)(x + (size_t)row * CDIM);
    float4 v = xr[tid];
    float s  = v.x + v.y + v.z + v.w;
    float ss = v.x*v.x + v.y*v.y + v.z*v.z + v.w*v.w;

    __shared__ float red_s[8], red_ss[8];
    __shared__ float s_mu, s_rstd;
    int lane = tid & 31, wid = tid >> 5;
    s = warp_sum(s); ss = warp_sum(ss);
    if (lane == 0) { red_s[wid] = s; red_ss[wid] = ss; }
    __syncthreads();
    if (tid == 0) {
        float ts = 0.f, tss = 0.f;
        #pragma unroll
        for (int i = 0; i < 8; i++) { ts += red_s[i]; tss += red_ss[i]; }
        float mu  = ts * (1.0f / CDIM);
        float var = tss * (1.0f / CDIM) - mu * mu;
        s_mu = mu; s_rstd = rsqrtf(var + 1e-5f);
    }
    __syncthreads();
    float mu = s_mu, rstd = s_rstd;
    float4 w4 = ((const float4*)w)[tid], b4 = ((const float4*)b)[tid];
    float4 o;
    o.x = (v.x - mu) * rstd * w4.x + b4.x;
    o.y = (v.y - mu) * rstd * w4.y + b4.y;
    o.z = (v.z - mu) * rstd * w4.z + b4.z;
    o.w = (v.w - mu) * rstd * w4.w + b4.w;
    ((float4*)(y + (size_t)row * CDIM))[tid] = o;
}

// ===================== split conversion (activations) =====================
__global__ void conv_split_kernel(const float* __restrict__ x,
                                  __nv_bfloat16* __restrict__ hi,
                                  __nv_bfloat16* __restrict__ lo, int n) {
    int i = (blockIdx.x * blockDim.x + threadIdx.x) * 4;
    if (i >= n) return;
    float4 v = *(const float4*)(x + i);
    __nv_bfloat16 h0 = __float2bfloat16(v.x);
    __nv_bfloat16 h1 = __float2bfloat16(v.y);
    __nv_bfloat16 h2 = __float2bfloat16(v.z);
    __nv_bfloat16 h3 = __float2bfloat16(v.w);
    __nv_bfloat16 l0 = __float2bfloat16(v.x - __bfloat162float(h0));
    __nv_bfloat16 l1 = __float2bfloat16(v.y - __bfloat162float(h1));
    __nv_bfloat16 l2 = __float2bfloat16(v.z - __bfloat162float(h2));
    __nv_bfloat16 l3 = __float2bfloat16(v.w - __bfloat162float(h3));
    __nv_bfloat162 p;
    p.x = h0; p.y = h1; *((__nv_bfloat162*)(hi + i))     = p;
    p.x = h2; p.y = h3; *((__nv_bfloat162*)(hi + i + 2)) = p;
    p.x = l0; p.y = l1; *((__nv_bfloat162*)(lo + i))     = p;
    p.x = l2; p.y = l3; *((__nv_bfloat162*)(lo + i + 2)) = p;
}

// ===================== weight transpose + split: W[K,N] -> Wt[N,K] hi/lo =====================
__global__ void transpose_split_kernel(const float* __restrict__ W,
                                       __nv_bfloat16* __restrict__ Th,
                                       __nv_bfloat16* __restrict__ Tl, int K, int N) {
    __shared__ float t[32][33];
    int n0 = blockIdx.x * 32, k0 = blockIdx.y * 32;
    int tx = threadIdx.x;
    for (int i = threadIdx.y; i < 32; i += 8)
        t[i][tx] = W[(size_t)(k0 + i) * N + n0 + tx];
    __syncthreads();
    for (int i = threadIdx.y; i < 32; i += 8) {
        float x = t[tx][i];                  // = W[k0+tx][n0+i]
        __nv_bfloat16 h = __float2bfloat16(x);
        __nv_bfloat16 l = __float2bfloat16(x - __bfloat162float(h));
        size_t oi = (size_t)(n0 + i) * K + k0 + tx;
        Th[oi] = h; Tl[oi] = l;
    }
}

// ===================== wmma GEMM: C[M,N] = A[M,K] @ Wt[N,K]^T (raw, no epilogue) =====================
// CTA 128x128, 8 warps (4 m-bands x 2 n-bands), warp tile 32x64 (2x4 wmma tiles), BK=32.
// Split bf16: 3 accumulation terms aH*bH + aH*bL + aL*bH.
#define BK    32
#define LDT   40   // padded row stride in bf16 (80 B -> conflict-free ldmatrix)

__global__ __launch_bounds__(256) void gemm_wmma_kernel(
    const __nv_bfloat16* __restrict__ Ahi, const __nv_bfloat16* __restrict__ Alo,
    const __nv_bfloat16* __restrict__ Bhi, const __nv_bfloat16* __restrict__ Blo,
    float* __restrict__ C, int M, int N, int K)
{
    __shared__ __nv_bfloat16 As[2][128][LDT];   // [hi/lo][row][k]
    __shared__ __nv_bfloat16 Bs[2][128][LDT];   // [hi/lo][n-row][k]

    const int tid = threadIdx.x;
    const int wid = tid >> 5;
    const int wm = wid & 3;          // m band: rows wm*32 .. +31
    const int wn = wid >> 2;         // n band: cols wn*64 .. +63
    const size_t bm = (size_t)blockIdx.y * 128;
    const size_t bn = (size_t)blockIdx.x * 128;

    // loader indexing: 128 rows x 32 cols bf16 per tile; each thread: rows r, r+64 (8 bf16 each)
    const int lr  = tid >> 2;            // 0..63
    const int lc  = (tid & 3) * 8;       // 0,8,16,24

    wmma::fragment<wmma::accumulator, 16, 16, 16, float> acc[2][4];
    #pragma unroll
    for (int i = 0; i < 2; i++)
        #pragma unroll
        for (int j = 0; j < 4; j++)
            wmma::fill_fragment(acc[i][j], 0.0f);

    for (int k0 = 0; k0 < K; k0 += BK) {
        // load A/B hi+lo tiles
        const __nv_bfloat16* a0 = Ahi + (bm + lr) * K + k0 + lc;
        const __nv_bfloat16* a1 = Alo + (bm + lr) * K + k0 + lc;
        const __nv_bfloat16* b0 = Bhi + (bn + lr) * K + k0 + lc;
        const __nv_bfloat16* b1 = Blo + (bn + lr) * K + k0 + lc;
        const size_t s64 = (size_t)64 * K;
        *(uint4*)&As[0][lr][lc]      = *(const uint4*)(a0);
        *(uint4*)&As[0][lr+64][lc]   = *(const uint4*)(a0 + s64);
        *(uint4*)&As[1][lr][lc]      = *(const uint4*)(a1);
        *(uint4*)&As[1][lr+64][lc]   = *(const uint4*)(a1 + s64);
        *(uint4*)&Bs[0][lr][lc]      = *(const uint4*)(b0);
        *(uint4*)&Bs[0][lr+64][lc]   = *(const uint4*)(b0 + s64);
        *(uint4*)&Bs[1][lr][lc]      = *(const uint4*)(b1);
        *(uint4*)&Bs[1][lr+64][lc]   = *(const uint4*)(b1 + s64);
        __syncthreads();

        #pragma unroll
        for (int kk = 0; kk < BK; kk += 16) {
            wmma::fragment<wmma::matrix_a, 16, 16, 16, __nv_bfloat16, wmma::row_major> aH[2], aL[2];
            wmma::fragment<wmma::matrix_b, 16, 16, 16, __nv_bfloat16, wmma::col_major> bH[4], bL[4];
            #pragma unroll
            for (int i = 0; i < 2; i++) {
                wmma::load_matrix_sync(aH[i], &As[0][wm*32 + i*16][kk], LDT);
                wmma::load_matrix_sync(aL[i], &As[1][wm*32 + i*16][kk], LDT);
            }
            #pragma unroll
            for (int j = 0; j < 4; j++) {
                wmma::load_matrix_sync(bH[j], &Bs[0][wn*64 + j*16][kk], LDT);
                wmma::load_matrix_sync(bL[j], &Bs[1][wn*64 + j*16][kk], LDT);
            }
            #pragma unroll
            for (int i = 0; i < 2; i++)
                #pragma unroll
                for (int j = 0; j < 4; j++) {
                    wmma::mma_sync(acc[i][j], aH[i], bH[j], acc[i][j]);
                    wmma::mma_sync(acc[i][j], aH[i], bL[j], acc[i][j]);
                    wmma::mma_sync(acc[i][j], aL[i], bH[j], acc[i][j]);
                }
        }
        __syncthreads();
    }

    #pragma unroll
    for (int i = 0; i < 2; i++)
        #pragma unroll
        for (int j = 0; j < 4; j++) {
            float* dst = C + (bm + wm*32 + i*16) * N + bn + wn*64 + j*16;
            wmma::store_matrix_sync(dst, acc[i][j], N, wmma::mem_row_major);
        }
}

// ===================== pointwise epilogue: bias (+res) (+gelu), in-place capable =====================
__device__ __forceinline__ float gelu_exact(float x) {
    return x * 0.5f * (1.0f + erff(x * 0.70710678118654752f));
}

template<bool GELU, bool RES>
__global__ void epi_kernel(const float* __restrict__ Craw, const float* __restrict__ bias,
                           const float* __restrict__ res, float* __restrict__ out,
                           int nmask /* N-1, N power of 2 */) {
    int i = (blockIdx.x * blockDim.x + threadIdx.x) * 4;
    int col = i & nmask;
    float4 v = *(const float4*)(Craw + i);
    float4 b = *(const float4*)(bias + col);
    v.x += b.x; v.y += b.y; v.z += b.z; v.w += b.w;
    if (RES) {
        float4 r = *(const float4*)(res + i);
        v.x += r.x; v.y += r.y; v.z += r.z; v.w += r.w;
    }
    if (GELU) {
        v.x = gelu_exact(v.x); v.y = gelu_exact(v.y);
        v.z = gelu_exact(v.z); v.w = gelu_exact(v.w);
    }
    *(float4*)(out + i) = v;
}

// ===================== Fused flash-style attention (fp32 SIMT) =====================
__global__ __launch_bounds__(256) void attn_kernel(
    const float* __restrict__ Q, const float* __restrict__ K,
    const float* __restrict__ V, float* __restrict__ O)
{
    int bh = blockIdx.y;
    int b  = bh / HEADS;
    int h  = bh % HEADS;
    int q0 = blockIdx.x * 64;

    __shared__ float Qs[64][64];
    __shared__ float Kt[64][36];    // transposed K tile: [d][j], padded
    __shared__ float Vs[32][64];
    __shared__ float Ss[64][36];    // padded
    __shared__ float m_s[64], l_s[64], f_s[64];

    int tid = threadIdx.x;
    int tx = tid & 15, ty = tid >> 4;
    const float scale = 0.125f;

    #pragma unroll
    for (int i = 0; i < 4; i++) {
        int f = tid + i * 256;
        int r = f >> 4, c4 = (f & 15) * 4;
        *(float4*)&Qs[r][c4] =
            *(const float4*)(Q + ((size_t)(b*SEQ + q0 + r) * CDIM + h*HDIM + c4));
    }
    if (tid < 64) { m_s[tid] = -1e30f; l_s[tid] = 0.f; }

    float acc[4][4] = {};
    __syncthreads();

    for (int kv0 = 0; kv0 < SEQ; kv0 += 32) {
        #pragma unroll
        for (int i = 0; i < 2; i++) {
            int f = tid + i * 256;
            int r = f >> 4, c4 = (f & 15) * 4;
            size_t gidx = (size_t)(b*SEQ + kv0 + r) * CDIM + h*HDIM + c4;
            float4 kk = *(const float4*)(K + gidx);
            Kt[c4+0][r] = kk.x; Kt[c4+1][r] = kk.y;
            Kt[c4+2][r] = kk.z; Kt[c4+3][r] = kk.w;
            *(float4*)&Vs[r][c4] = *(const float4*)(V + gidx);
        }
        __syncthreads();

        {
            int rg = tid >> 3;
            int c  = (tid & 7) * 4;
            int r0 = rg * 2;
            float s00=0,s01=0,s02=0,s03=0;
            float s10=0,s11=0,s12=0,s13=0;
            #pragma unroll 8
            for (int k = 0; k < 64; k++) {
                float4 kv = *(float4*)&Kt[k][c];
                float a0 = Qs[r0][k];
                float a1 = Qs[r0+1][k];
                s00 += a0*kv.x; s01 += a0*kv.y; s02 += a0*kv.z; s03 += a0*kv.w;
                s10 += a1*kv.x; s11 += a1*kv.y; s12 += a1*kv.z; s13 += a1*kv.w;
            }
            *(float4*)&Ss[r0][c]   = make_float4(s00*scale, s01*scale, s02*scale, s03*scale);
            *(float4*)&Ss[r0+1][c] = make_float4(s10*scale, s11*scale, s12*scale, s13*scale);
        }
        __syncthreads();

        if (tid < 64) {
            float m_old = m_s[tid];
            float mx = m_old;
            #pragma unroll 8
            for (int j = 0; j < 32; j++) mx = fmaxf(mx, Ss[tid][j]);
            float fac = __expf(m_old - mx);
            float sum = 0.f;
            #pragma unroll 8
            for (int j = 0; j < 32; j++) {
                float p = __expf(Ss[tid][j] - mx);
                Ss[tid][j] = p;
                sum += p;
            }
            l_s[tid] = l_s[tid] * fac + sum;
            m_s[tid] = mx;
            f_s[tid] = fac;
        }
        __syncthreads();

        #pragma unroll
        for (int i = 0; i < 4; i++) {
            float fc = f_s[ty*4+i];
            acc[i][0] *= fc; acc[i][1] *= fc; acc[i][2] *= fc; acc[i][3] *= fc;
        }
        #pragma unroll 4
        for (int k = 0; k < 32; k++) {
            float4 v = *(float4*)&Vs[k][tx*4];
            float p0 = Ss[ty*4+0][k];
            float p1 = Ss[ty*4+1][k];
            float p2 = Ss[ty*4+2][k];
            float p3 = Ss[ty*4+3][k];
            acc[0][0] += p0*v.x; acc[0][1] += p0*v.y; acc[0][2] += p0*v.z; acc[0][3] += p0*v.w;
            acc[1][0] += p1*v.x; acc[1][1] += p1*v.y; acc[1][2] += p1*v.z; acc[1][3] += p1*v.w;
            acc[2][0] += p2*v.x; acc[2][1] += p2*v.y; acc[2][2] += p2*v.z; acc[2][3] += p2*v.w;
            acc[3][0] += p3*v.x; acc[3][1] += p3*v.y; acc[3][2] += p3*v.z; acc[3][3] += p3*v.w;
        }
        __syncthreads();
    }

    #pragma unroll
    for (int i = 0; i < 4; i++) {
        int r = q0 + ty*4 + i;
        float inv_l = 1.0f / l_s[ty*4+i];
        float4 o = make_float4(acc[i][0]*inv_l, acc[i][1]*inv_l,
                               acc[i][2]*inv_l, acc[i][3]*inv_l);
        *(float4*)(O + ((size_t)(b*SEQ + r) * CDIM + h*HDIM + tx*4)) = o;
    }
}

// ===================== host =====================
static inline void conv(const float* src, __nv_bfloat16* hi, __nv_bfloat16* lo, int n) {
    conv_split_kernel<<<n / 1024, 256>>>(src, hi, lo, n);
}
static inline void transp(const float* W, __nv_bfloat16* th, __nv_bfloat16* tl, int K, int N) {
    transpose_split_kernel<<<dim3(N / 32, K / 32), dim3(32, 8)>>>(W, th, tl, K, N);
}

extern "C" void kernel_launch(void* const* d_in, const int* in_sizes, int n_in,
                              void* d_out, int out_size)
{
    const float* x      = (const float*)d_in[0];
    const float* wq     = (const float*)d_in[1];
    const float* bq     = (const float*)d_in[2];
    const float* wk     = (const float*)d_in[3];
    const float* bk     = (const float*)d_in[4];
    const float* wv     = (const float*)d_in[5];
    const float* bv     = (const float*)d_in[6];
    const float* wo     = (const float*)d_in[7];
    const float* bo     = (const float*)d_in[8];
    const float* ln1_w  = (const float*)d_in[9];
    const float* ln1_b  = (const float*)d_in[10];
    const float* ln2_w  = (const float*)d_in[11];
    const float* ln2_b  = (const float*)d_in[12];
    const float* fc1_w  = (const float*)d_in[13];
    const float* fc1_b  = (const float*)d_in[14];
    const float* fc2_w  = (const float*)d_in[15];
    const float* fc2_b  = (const float*)d_in[16];
    const float* wout   = (const float*)d_in[17];
    const float* bout   = (const float*)d_in[18];
    const float* lnout_w= (const float*)d_in[19];
    const float* lnout_b= (const float*)d_in[20];
    float* out = (float*)d_out;

    float *h1, *q, *k, *v, *o, *h2, *h3, *f1;
    __nv_bfloat16 *ahi, *alo, *wthi, *wtlo;
    cudaGetSymbolAddress((void**)&h1, g_h1);
    cudaGetSymbolAddress((void**)&q,  g_q);
    cudaGetSymbolAddress((void**)&k,  g_k);
    cudaGetSymbolAddress((void**)&v,  g_v);
    cudaGetSymbolAddress((void**)&o,  g_o);
    cudaGetSymbolAddress((void**)&h2, g_h2);
    cudaGetSymbolAddress((void**)&h3, g_h3);
    cudaGetSymbolAddress((void**)&f1, g_f1);
    cudaGetSymbolAddress((void**)&ahi, g_ahi);
    cudaGetSymbolAddress((void**)&alo, g_alo);
    cudaGetSymbolAddress((void**)&wthi, g_wthi);
    cudaGetSymbolAddress((void**)&wtlo, g_wtlo);

    dim3 blk(256);
    dim3 gc(CDIM/128, ROWS/128);   // (8, 32)
    dim3 gf(FF/128,   ROWS/128);   // (32, 32)
    const int nepi_c = ROWS*CDIM/1024;   // pointwise epilogue blocks (N=1024 outputs)
    const int nepi_f = ROWS*FF/1024;

    // 1. h1 = LN1(x)
    ln_kernel<<<ROWS, blk>>>(x, ln1_w, ln1_b, h1);
    // 2. split-convert A = h1
    conv(h1, ahi, alo, ROWS*CDIM);
    // 3-5. QKV projections
    transp(wq, wthi, wtlo, CDIM, CDIM);
    gemm_wmma_kernel<<<gc, blk>>>(ahi, alo, wthi, wtlo, q, ROWS, CDIM, CDIM);
    epi_kernel<false,false><<<nepi_c, blk>>>(q, bq, nullptr, q, CDIM-1);
    transp(wk, wthi, wtlo, CDIM, CDIM);
    gemm_wmma_kernel<<<gc, blk>>>(ahi, alo, wthi, wtlo, k, ROWS, CDIM, CDIM);
    epi_kernel<false,false><<<nepi_c, blk>>>(k, bk, nullptr, k, CDIM-1);
    transp(wv, wthi, wtlo, CDIM, CDIM);
    gemm_wmma_kernel<<<gc, blk>>>(ahi, alo, wthi, wtlo, v, ROWS, CDIM, CDIM);
    epi_kernel<false,false><<<nepi_c, blk>>>(v, bv, nullptr, v, CDIM-1);
    // 6. attention
    attn_kernel<<<dim3(SEQ/64, BATCH*HEADS), blk>>>(q, k, v, o);
    // 7. h2 = o @ wo + bo + x
    conv(o, ahi, alo, ROWS*CDIM);
    transp(wo, wthi, wtlo, CDIM, CDIM);
    gemm_wmma_kernel<<<gc, blk>>>(ahi, alo, wthi, wtlo, h2, ROWS, CDIM, CDIM);
    epi_kernel<false,true><<<nepi_c, blk>>>(h2, bo, x, h2, CDIM-1);
    // 8. h3 = LN2(h2)
    ln_kernel<<<ROWS, blk>>>(h2, ln2_w, ln2_b, h3);
    // 9. f1 = gelu(h3 @ fc1_w + fc1_b)
    conv(h3, ahi, alo, ROWS*CDIM);
    transp(fc1_w, wthi, wtlo, CDIM, FF);
    gemm_wmma_kernel<<<gf, blk>>>(ahi, alo, wthi, wtlo, f1, ROWS, FF, CDIM);
    epi_kernel<true,false><<<nepi_f, blk>>>(f1, fc1_b, nullptr, f1, FF-1);
    // 10. h4 = f1 @ fc2_w + fc2_b + h2   (into h1)
    conv(f1, ahi, alo, ROWS*FF);
    transp(fc2_w, wthi, wtlo, FF, CDIM);
    gemm_wmma_kernel<<<gc, blk>>>(ahi, alo, wthi, wtlo, h1, ROWS, CDIM, FF);
    epi_kernel<false,true><<<nepi_c, blk>>>(h1, fc2_b, h2, h1, CDIM-1);
    // 11. h5 = h4 @ wout + bout          (into h3)
    conv(h1, ahi, alo, ROWS*CDIM);
    transp(wout, wthi, wtlo, CDIM, CDIM);
    gemm_wmma_kernel<<<gc, blk>>>(ahi, alo, wthi, wtlo, h3, ROWS, CDIM, CDIM);
    epi_kernel<false,false><<<nepi_c, blk>>>(h3, bout, nullptr, h3, CDIM-1);
    // 12. out = LN(h5)
    ln_kernel<<<ROWS, blk>>>(h3, lnout_w, lnout_b, out);
}

// round 6
// speedup vs baseline: 1.8355x; 1.8355x over previous
#include <cuda_runtime.h>
#include <cuda_bf16.h>
#include <mma.h>
#include <math.h>
#include <stdint.h>

using namespace nvcuda;

// Problem constants: B=2, N=2048, C=1024, H=16, D=64
#define BATCH 2
#define SEQ   2048
#define CDIM  1024
#define HEADS 16
#define HDIM  64
#define ROWS  (BATCH*SEQ)          // 4096
#define FF    (4*CDIM)             // 4096

// ---------------- scratch (static device globals; no allocs allowed) ----------------
__device__ float g_raw[(size_t)ROWS*FF];    // raw GEMM output (fp32), max 4096x4096
__device__ float g_h2 [(size_t)ROWS*CDIM];  // post-attn residual (fp32); reused for h5
__device__ __nv_bfloat16 g_ah[(size_t)ROWS*FF];    // activation hi (A operand)
__device__ __nv_bfloat16 g_al[(size_t)ROWS*FF];    // activation lo
__device__ __nv_bfloat16 g_wth[(size_t)FF*CDIM];   // transposed weight hi
__device__ __nv_bfloat16 g_wtl[(size_t)FF*CDIM];   // transposed weight lo
__device__ __nv_bfloat16 g_qh[(size_t)ROWS*CDIM], g_ql[(size_t)ROWS*CDIM];
__device__ __nv_bfloat16 g_kh[(size_t)ROWS*CDIM], g_kl[(size_t)ROWS*CDIM];
__device__ __nv_bfloat16 g_vh[(size_t)ROWS*CDIM], g_vl[(size_t)ROWS*CDIM];
__device__ __nv_bfloat16 g_oh[(size_t)ROWS*CDIM], g_ol[(size_t)ROWS*CDIM];

// ===================== small device helpers =====================
__device__ __forceinline__ uint32_t smem_u32(const void* p) {
    return (uint32_t)__cvta_generic_to_shared(p);
}
__device__ __forceinline__ uint32_t packbf(float lo, float hi) {
    uint32_t r;
    asm("cvt.rn.bf16x2.f32 %0, %1, %2;" : "=r"(r) : "f"(hi), "f"(lo));
    return r;
}
__device__ __forceinline__ void mma16816(float* d, const uint32_t* a, uint32_t b0, uint32_t b1) {
    asm volatile(
        "mma.sync.aligned.m16n8k16.row.col.f32.bf16.bf16.f32 "
        "{%0,%1,%2,%3}, {%4,%5,%6,%7}, {%8,%9}, {%0,%1,%2,%3};\n"
        : "+f"(d[0]), "+f"(d[1]), "+f"(d[2]), "+f"(d[3])
        : "r"(a[0]), "r"(a[1]), "r"(a[2]), "r"(a[3]), "r"(b0), "r"(b1));
}
__device__ __forceinline__ void ldsm_x2(uint32_t& r0, uint32_t& r1, uint32_t addr) {
    asm volatile("ldmatrix.sync.aligned.m8n8.x2.shared.b16 {%0,%1}, [%2];"
                 : "=r"(r0), "=r"(r1) : "r"(addr));
}
__device__ __forceinline__ void ldsm_x2_t(uint32_t& r0, uint32_t& r1, uint32_t addr) {
    asm volatile("ldmatrix.sync.aligned.m8n8.x2.trans.shared.b16 {%0,%1}, [%2];"
                 : "=r"(r0), "=r"(r1) : "r"(addr));
}
__device__ __forceinline__ void cpa16(uint32_t dst, const void* src) {
    asm volatile("cp.async.cg.shared.global [%0], [%1], 16;" :: "r"(dst), "l"(src));
}
__device__ __forceinline__ float gelu_exact(float x) {
    return x * 0.5f * (1.0f + erff(x * 0.70710678118654752f));
}
__inline__ __device__ float warp_sum(float v) {
    #pragma unroll
    for (int o = 16; o > 0; o >>= 1) v += __shfl_xor_sync(0xffffffffu, v, o);
    return v;
}

// ===================== LayerNorm (fp32 out, for final) =====================
__global__ void ln_kernel(const float* __restrict__ x, const float* __restrict__ w,
                          const float* __restrict__ b, float* __restrict__ y) {
    int row = blockIdx.x;
    int tid = threadIdx.x;
    const float4* xr = (const float4*)(x + (size_t)row * CDIM);
    float4 v = xr[tid];
    float s  = v.x + v.y + v.z + v.w;
    float ss = v.x*v.x + v.y*v.y + v.z*v.z + v.w*v.w;
    __shared__ float red_s[8], red_ss[8];
    __shared__ float s_mu, s_rstd;
    int lane = tid & 31, wid = tid >> 5;
    s = warp_sum(s); ss = warp_sum(ss);
    if (lane == 0) { red_s[wid] = s; red_ss[wid] = ss; }
    __syncthreads();
    if (tid == 0) {
        float ts = 0.f, tss = 0.f;
        #pragma unroll
        for (int i = 0; i < 8; i++) { ts += red_s[i]; tss += red_ss[i]; }
        float mu  = ts * (1.0f / CDIM);
        float var = tss * (1.0f / CDIM) - mu * mu;
        s_mu = mu; s_rstd = rsqrtf(var + 1e-5f);
    }
    __syncthreads();
    float mu = s_mu, rstd = s_rstd;
    float4 w4 = ((const float4*)w)[tid], b4 = ((const float4*)b)[tid];
    float4 o;
    o.x = (v.x - mu) * rstd * w4.x + b4.x;
    o.y = (v.y - mu) * rstd * w4.y + b4.y;
    o.z = (v.z - mu) * rstd * w4.z + b4.z;
    o.w = (v.w - mu) * rstd * w4.w + b4.w;
    ((float4*)(y + (size_t)row * CDIM))[tid] = o;
}

// ===================== LayerNorm -> split bf16 =====================
__global__ void ln_split_kernel(const float* __restrict__ x, const float* __restrict__ w,
                                const float* __restrict__ b,
                                __nv_bfloat16* __restrict__ yh, __nv_bfloat16* __restrict__ yl) {
    int row = blockIdx.x;
    int tid = threadIdx.x;
    const float4* xr = (const float4*)(x + (size_t)row * CDIM);
    float4 v = xr[tid];
    float s  = v.x + v.y + v.z + v.w;
    float ss = v.x*v.x + v.y*v.y + v.z*v.z + v.w*v.w;
    __shared__ float red_s[8], red_ss[8];
    __shared__ float s_mu, s_rstd;
    int lane = tid & 31, wid = tid >> 5;
    s = warp_sum(s); ss = warp_sum(ss);
    if (lane == 0) { red_s[wid] = s; red_ss[wid] = ss; }
    __syncthreads();
    if (tid == 0) {
        float ts = 0.f, tss = 0.f;
        #pragma unroll
        for (int i = 0; i < 8; i++) { ts += red_s[i]; tss += red_ss[i]; }
        float mu  = ts * (1.0f / CDIM);
        float var = tss * (1.0f / CDIM) - mu * mu;
        s_mu = mu; s_rstd = rsqrtf(var + 1e-5f);
    }
    __syncthreads();
    float mu = s_mu, rstd = s_rstd;
    float4 w4 = ((const float4*)w)[tid], b4 = ((const float4*)b)[tid];
    float o[4];
    o[0] = (v.x - mu) * rstd * w4.x + b4.x;
    o[1] = (v.y - mu) * rstd * w4.y + b4.y;
    o[2] = (v.z - mu) * rstd * w4.z + b4.z;
    o[3] = (v.w - mu) * rstd * w4.w + b4.w;
    size_t base = (size_t)row * CDIM + tid * 4;
    #pragma unroll
    for (int i = 0; i < 4; i += 2) {
        uint32_t hp = packbf(o[i], o[i+1]);
        __nv_bfloat162 hv = *reinterpret_cast<__nv_bfloat162*>(&hp);
        float r0 = o[i]   - __bfloat162float(hv.x);
        float r1 = o[i+1] - __bfloat162float(hv.y);
        uint32_t lp = packbf(r0, r1);
        *(uint32_t*)&yh[base + i] = hp;
        *(uint32_t*)&yl[base + i] = lp;
    }
}

// ===================== weight transpose + split: W[K,N] -> Wt[N,K] hi/lo =====================
__global__ void transpose_split_kernel(const float* __restrict__ W,
                                       __nv_bfloat16* __restrict__ Th,
                                       __nv_bfloat16* __restrict__ Tl, int K, int N) {
    __shared__ float t[32][33];
    int n0 = blockIdx.x * 32, k0 = blockIdx.y * 32;
    int tx = threadIdx.x;
    for (int i = threadIdx.y; i < 32; i += 8)
        t[i][tx] = W[(size_t)(k0 + i) * N + n0 + tx];
    __syncthreads();
    for (int i = threadIdx.y; i < 32; i += 8) {
        float x = t[tx][i];
        __nv_bfloat16 h = __float2bfloat16(x);
        __nv_bfloat16 l = __float2bfloat16(x - __bfloat162float(h));
        size_t oi = (size_t)(n0 + i) * K + k0 + tx;
        Th[oi] = h; Tl[oi] = l;
    }
}

// ===================== wmma GEMM (cp.async double-buffered): C = A @ Wt^T (raw fp32) =====================
#define BK    32
#define LDT   40   // padded row stride in bf16 (80B = 5x16B, 16B-aligned rows)
#define GEMM_SMEM (2*2*128*LDT*2*2)   // 2 buf x 2 hl x 128 x LDT x 2B x {A,B} = 81920

__global__ __launch_bounds__(256) void gemm_wmma_kernel(
    const __nv_bfloat16* __restrict__ Ahi, const __nv_bfloat16* __restrict__ Alo,
    const __nv_bfloat16* __restrict__ Bhi, const __nv_bfloat16* __restrict__ Blo,
    float* __restrict__ C, int M, int N, int K)
{
    extern __shared__ __nv_bfloat16 dsm[];
    __nv_bfloat16* Asm = dsm;                    // [buf][hl][128][LDT]
    __nv_bfloat16* Bsm = dsm + 2*2*128*LDT;

    const int tid = threadIdx.x;
    const int wid = tid >> 5;
    const int wm = wid & 3;          // m band: rows wm*32..+31
    const int wn = wid >> 2;         // n band: cols wn*64..+63
    const size_t bm = (size_t)blockIdx.y * 128;
    const size_t bn = (size_t)blockIdx.x * 128;

    const int lr = tid >> 2;             // 0..63
    const int lc = (tid & 3) * 8;        // 0,8,16,24

    const uint32_t sA = smem_u32(Asm);
    const uint32_t sB = smem_u32(Bsm);
    const size_t s64 = (size_t)64 * K;

    auto fill = [&](int buf, int k0) {
        const __nv_bfloat16* a0 = Ahi + (bm + lr) * K + k0 + lc;
        const __nv_bfloat16* a1 = Alo + (bm + lr) * K + k0 + lc;
        const __nv_bfloat16* b0 = Bhi + (bn + lr) * K + k0 + lc;
        const __nv_bfloat16* b1 = Blo + (bn + lr) * K + k0 + lc;
        uint32_t dA0 = sA + (((buf*2+0)*128 + lr)*LDT + lc)*2;
        uint32_t dA1 = sA + (((buf*2+1)*128 + lr)*LDT + lc)*2;
        uint32_t dB0 = sB + (((buf*2+0)*128 + lr)*LDT + lc)*2;
        uint32_t dB1 = sB + (((buf*2+1)*128 + lr)*LDT + lc)*2;
        const uint32_t r64 = 64*LDT*2;
        cpa16(dA0, a0);           cpa16(dA0 + r64, a0 + s64);
        cpa16(dA1, a1);           cpa16(dA1 + r64, a1 + s64);
        cpa16(dB0, b0);           cpa16(dB0 + r64, b0 + s64);
        cpa16(dB1, b1);           cpa16(dB1 + r64, b1 + s64);
        asm volatile("cp.async.commit_group;");
    };

    wmma::fragment<wmma::accumulator, 16, 16, 16, float> acc[2][4];
    #pragma unroll
    for (int i = 0; i < 2; i++)
        #pragma unroll
        for (int j = 0; j < 4; j++)
            wmma::fill_fragment(acc[i][j], 0.0f);

    const int nch = K / BK;
    fill(0, 0);
    int buf = 0;
    for (int ch = 0; ch < nch; ch++) {
        if (ch + 1 < nch) {
            fill(buf ^ 1, (ch + 1) * BK);
            asm volatile("cp.async.wait_group 1;");
        } else {
            asm volatile("cp.async.wait_group 0;");
        }
        __syncthreads();

        const __nv_bfloat16* Ah = Asm + (buf*2+0)*128*LDT;
        const __nv_bfloat16* Al = Asm + (buf*2+1)*128*LDT;
        const __nv_bfloat16* Bh = Bsm + (buf*2+0)*128*LDT;
        const __nv_bfloat16* Bl = Bsm + (buf*2+1)*128*LDT;

        #pragma unroll
        for (int kk = 0; kk < BK; kk += 16) {
            wmma::fragment<wmma::matrix_a, 16, 16, 16, __nv_bfloat16, wmma::row_major> aH[2], aL[2];
            wmma::fragment<wmma::matrix_b, 16, 16, 16, __nv_bfloat16, wmma::col_major> bH[4], bL[4];
            #pragma unroll
            for (int i = 0; i < 2; i++) {
                wmma::load_matrix_sync(aH[i], Ah + (wm*32 + i*16)*LDT + kk, LDT);
                wmma::load_matrix_sync(aL[i], Al + (wm*32 + i*16)*LDT + kk, LDT);
            }
            #pragma unroll
            for (int j = 0; j < 4; j++) {
                wmma::load_matrix_sync(bH[j], Bh + (wn*64 + j*16)*LDT + kk, LDT);
                wmma::load_matrix_sync(bL[j], Bl + (wn*64 + j*16)*LDT + kk, LDT);
            }
            #pragma unroll
            for (int i = 0; i < 2; i++)
                #pragma unroll
                for (int j = 0; j < 4; j++) {
                    wmma::mma_sync(acc[i][j], aH[i], bH[j], acc[i][j]);
                    wmma::mma_sync(acc[i][j], aH[i], bL[j], acc[i][j]);
                    wmma::mma_sync(acc[i][j], aL[i], bH[j], acc[i][j]);
                }
        }
        __syncthreads();
        buf ^= 1;
    }

    #pragma unroll
    for (int i = 0; i < 2; i++)
        #pragma unroll
        for (int j = 0; j < 4; j++) {
            float* dst = C + (bm + wm*32 + i*16) * N + bn + wn*64 + j*16;
            wmma::store_matrix_sync(dst, acc[i][j], N, wmma::mem_row_major);
        }
}

// ===================== epilogues =====================
// raw + bias (+res) (+gelu) -> split bf16
template<bool GELU, bool RES>
__global__ void epi_split_kernel(const float* __restrict__ Craw, const float* __restrict__ bias,
                                 const float* __restrict__ res,
                                 __nv_bfloat16* __restrict__ oh, __nv_bfloat16* __restrict__ ol,
                                 int nmask) {
    int i = (blockIdx.x * blockDim.x + threadIdx.x) * 4;
    int col = i & nmask;
    float4 v = *(const float4*)(Craw + i);
    float4 b = *(const float4*)(bias + col);
    float o[4] = {v.x + b.x, v.y + b.y, v.z + b.z, v.w + b.w};
    if (RES) {
        float4 r = *(const float4*)(res + i);
        o[0] += r.x; o[1] += r.y; o[2] += r.z; o[3] += r.w;
    }
    if (GELU) {
        #pragma unroll
        for (int j = 0; j < 4; j++) o[j] = gelu_exact(o[j]);
    }
    #pragma unroll
    for (int j = 0; j < 4; j += 2) {
        uint32_t hp = packbf(o[j], o[j+1]);
        __nv_bfloat162 hv = *reinterpret_cast<__nv_bfloat162*>(&hp);
        float r0 = o[j]   - __bfloat162float(hv.x);
        float r1 = o[j+1] - __bfloat162float(hv.y);
        uint32_t lp = packbf(r0, r1);
        *(uint32_t*)&oh[i + j] = hp;
        *(uint32_t*)&ol[i + j] = lp;
    }
}

// raw + bias (+res) -> fp32
template<bool RES>
__global__ void epi_plain_kernel(const float* __restrict__ Craw, const float* __restrict__ bias,
                                 const float* __restrict__ res, float* __restrict__ out,
                                 int nmask) {
    int i = (blockIdx.x * blockDim.x + threadIdx.x) * 4;
    int col = i & nmask;
    float4 v = *(const float4*)(Craw + i);
    float4 b = *(const float4*)(bias + col);
    v.x += b.x; v.y += b.y; v.z += b.z; v.w += b.w;
    if (RES) {
        float4 r = *(const float4*)(res + i);
        v.x += r.x; v.y += r.y; v.z += r.z; v.w += r.w;
    }
    *(float4*)(out + i) = v;
}

// ===================== tensor-core flash attention =====================
// grid: (SEQ/64, BATCH*HEADS), 128 threads (4 warps). Warp w: Q rows [64*blk + 16w, +16).
// KV tile = 64. Split bf16, 3 MMA terms. S frags & P stay in registers (FA2 layout).
#define AP 72   // smem pitch (bf16) for K/V tiles: 144B, 16B-aligned, ldsm conflict-free

__global__ __launch_bounds__(128) void attn_mma_kernel(
    const __nv_bfloat16* __restrict__ qh, const __nv_bfloat16* __restrict__ ql,
    const __nv_bfloat16* __restrict__ kh, const __nv_bfloat16* __restrict__ kl,
    const __nv_bfloat16* __restrict__ vh, const __nv_bfloat16* __restrict__ vl,
    __nv_bfloat16* __restrict__ oh, __nv_bfloat16* __restrict__ ol)
{
    __shared__ __nv_bfloat16 Ksh[64][AP], Ksl[64][AP], Vsh[64][AP], Vsl[64][AP];

    const int tid = threadIdx.x, wid = tid >> 5, lane = tid & 31;
    const int g = lane >> 2, tig = lane & 3;
    const int bh = blockIdx.y, b = bh / HEADS, h = bh % HEADS;
    const int q0 = blockIdx.x * 64;
    const int hcol = h * HDIM;
    const size_t qrow = (size_t)b * SEQ + q0 + wid * 16;

    // preload Q fragments (A operand, rows g/g+8, 4 k-steps, hi+lo)
    uint32_t aQh[4][4], aQl[4][4];
    {
        const size_t r0 = (qrow + g) * CDIM, r1 = (qrow + g + 8) * CDIM;
        #pragma unroll
        for (int kk = 0; kk < 4; kk++) {
            int c0 = hcol + kk * 16 + 2 * tig, c1 = c0 + 8;
            aQh[kk][0] = *(const uint32_t*)&qh[r0 + c0];
            aQh[kk][1] = *(const uint32_t*)&qh[r1 + c0];
            aQh[kk][2] = *(const uint32_t*)&qh[r0 + c1];
            aQh[kk][3] = *(const uint32_t*)&qh[r1 + c1];
            aQl[kk][0] = *(const uint32_t*)&ql[r0 + c0];
            aQl[kk][1] = *(const uint32_t*)&ql[r1 + c0];
            aQl[kk][2] = *(const uint32_t*)&ql[r0 + c1];
            aQl[kk][3] = *(const uint32_t*)&ql[r1 + c1];
        }
    }

    const uint32_t kshb = smem_u32(&Ksh[0][0]);
    const uint32_t kslb = smem_u32(&Ksl[0][0]);
    const uint32_t vshb = smem_u32(&Vsh[0][0]);
    const uint32_t vslb = smem_u32(&Vsl[0][0]);
    const int rsub  = lane & 7;
    const int chalf = ((lane >> 3) & 1) * 8;
    const int rv    = lane & 15;

    float of[8][4];
    #pragma unroll
    for (int j = 0; j < 8; j++) { of[j][0]=0.f; of[j][1]=0.f; of[j][2]=0.f; of[j][3]=0.f; }
    float m0 = -1e30f, m1 = -1e30f, l0 = 0.f, l1 = 0.f;

    for (int kv0 = 0; kv0 < SEQ; kv0 += 64) {
        // load K/V tiles (64 x 64 bf16, hi+lo)
        #pragma unroll
        for (int i = 0; i < 4; i++) {
            int idx = tid + i * 128;
            int r = idx >> 3, c8 = (idx & 7) * 8;
            size_t gsrc = ((size_t)b * SEQ + kv0 + r) * CDIM + hcol + c8;
            *(uint4*)&Ksh[r][c8] = *(const uint4*)&kh[gsrc];
            *(uint4*)&Ksl[r][c8] = *(const uint4*)&kl[gsrc];
            *(uint4*)&Vsh[r][c8] = *(const uint4*)&vh[gsrc];
            *(uint4*)&Vsl[r][c8] = *(const uint4*)&vl[gsrc];
        }
        __syncthreads();

        // ---- S = Q @ K^T (split bf16, 3 terms) ----
        float s[8][4];
        #pragma unroll
        for (int nt = 0; nt < 8; nt++) { s[nt][0]=0.f; s[nt][1]=0.f; s[nt][2]=0.f; s[nt][3]=0.f; }
        #pragma unroll
        for (int kk = 0; kk < 4; kk++) {
            #pragma unroll
            for (int nt = 0; nt < 8; nt++) {
                uint32_t off = (uint32_t)(((nt*8 + rsub)*AP + kk*16 + chalf) * 2);
                uint32_t bh0, bh1, bl0, bl1;
                ldsm_x2(bh0, bh1, kshb + off);
                ldsm_x2(bl0, bl1, kslb + off);
                mma16816(s[nt], aQh[kk], bh0, bh1);
                mma16816(s[nt], aQh[kk], bl0, bl1);
                mma16816(s[nt], aQl[kk], bh0, bh1);
            }
        }

        // ---- online softmax on fragments ----
        float mx0 = -1e30f, mx1 = -1e30f;
        #pragma unroll
        for (int nt = 0; nt < 8; nt++) {
            s[nt][0] *= 0.125f; s[nt][1] *= 0.125f; s[nt][2] *= 0.125f; s[nt][3] *= 0.125f;
            mx0 = fmaxf(mx0, fmaxf(s[nt][0], s[nt][1]));
            mx1 = fmaxf(mx1, fmaxf(s[nt][2], s[nt][3]));
        }
        mx0 = fmaxf(mx0, __shfl_xor_sync(0xffffffffu, mx0, 1));
        mx0 = fmaxf(mx0, __shfl_xor_sync(0xffffffffu, mx0, 2));
        mx1 = fmaxf(mx1, __shfl_xor_sync(0xffffffffu, mx1, 1));
        mx1 = fmaxf(mx1, __shfl_xor_sync(0xffffffffu, mx1, 2));
        float m0n = fmaxf(m0, mx0), m1n = fmaxf(m1, mx1);
        float f0 = __expf(m0 - m0n), f1 = __expf(m1 - m1n);
        m0 = m0n; m1 = m1n;

        float ps0 = 0.f, ps1 = 0.f;
        #pragma unroll
        for (int nt = 0; nt < 8; nt++) {
            s[nt][0] = __expf(s[nt][0] - m0); ps0 += s[nt][0];
            s[nt][1] = __expf(s[nt][1] - m0); ps0 += s[nt][1];
            s[nt][2] = __expf(s[nt][2] - m1); ps1 += s[nt][2];
            s[nt][3] = __expf(s[nt][3] - m1); ps1 += s[nt][3];
        }
        ps0 += __shfl_xor_sync(0xffffffffu, ps0, 1);
        ps0 += __shfl_xor_sync(0xffffffffu, ps0, 2);
        ps1 += __shfl_xor_sync(0xffffffffu, ps1, 1);
        ps1 += __shfl_xor_sync(0xffffffffu, ps1, 2);
        l0 = l0 * f0 + ps0;
        l1 = l1 * f1 + ps1;

        #pragma unroll
        for (int j = 0; j < 8; j++) {
            of[j][0] *= f0; of[j][1] *= f0; of[j][2] *= f1; of[j][3] *= f1;
        }

        // ---- P -> split bf16 in registers (A-frag layout) ----
        uint32_t pha[8], phb[8], pla[8], plb[8];
        #pragma unroll
        for (int nt = 0; nt < 8; nt++) {
            uint32_t hp = packbf(s[nt][0], s[nt][1]);
            __nv_bfloat162 hv = *reinterpret_cast<__nv_bfloat162*>(&hp);
            pla[nt] = packbf(s[nt][0] - __bfloat162float(hv.x),
                             s[nt][1] - __bfloat162float(hv.y));
            pha[nt] = hp;
            uint32_t hp2 = packbf(s[nt][2], s[nt][3]);
            __nv_bfloat162 hv2 = *reinterpret_cast<__nv_bfloat162*>(&hp2);
            plb[nt] = packbf(s[nt][2] - __bfloat162float(hv2.x),
                             s[nt][3] - __bfloat162float(hv2.y));
            phb[nt] = hp2;
        }

        // ---- O += P @ V (split, 3 terms), V via ldmatrix.trans ----
        #pragma unroll
        for (int kk = 0; kk < 4; kk++) {
            uint32_t aH[4] = {pha[2*kk], phb[2*kk], pha[2*kk+1], phb[2*kk+1]};
            uint32_t aL[4] = {pla[2*kk], plb[2*kk], pla[2*kk+1], plb[2*kk+1]};
            #pragma unroll
            for (int j = 0; j < 8; j++) {
                uint32_t off = (uint32_t)(((kk*16 + rv)*AP + j*8) * 2);
                uint32_t bh0, bh1, bl0, bl1;
                ldsm_x2_t(bh0, bh1, vshb + off);
                ldsm_x2_t(bl0, bl1, vslb + off);
                mma16816(of[j], aH, bh0, bh1);
                mma16816(of[j], aH, bl0, bl1);
                mma16816(of[j], aL, bh0, bh1);
            }
        }
        __syncthreads();
    }

    // ---- epilogue: O /= l, write split bf16 ----
    float inv0 = 1.0f / l0, inv1 = 1.0f / l1;
    const size_t r0 = (qrow + g) * CDIM, r1 = (qrow + g + 8) * CDIM;
    #pragma unroll
    for (int j = 0; j < 8; j++) {
        int col = hcol + j * 8 + 2 * tig;
        float v0 = of[j][0] * inv0, v1 = of[j][1] * inv0;
        float v2 = of[j][2] * inv1, v3 = of[j][3] * inv1;
        uint32_t hp0 = packbf(v0, v1);
        __nv_bfloat162 h0 = *reinterpret_cast<__nv_bfloat162*>(&hp0);
        uint32_t lp0 = packbf(v0 - __bfloat162float(h0.x), v1 - __bfloat162float(h0.y));
        uint32_t hp1 = packbf(v2, v3);
        __nv_bfloat162 h1 = *reinterpret_cast<__nv_bfloat162*>(&hp1);
        uint32_t lp1 = packbf(v2 - __bfloat162float(h1.x), v3 - __bfloat162float(h1.y));
        *(uint32_t*)&oh[r0 + col] = hp0;
        *(uint32_t*)&ol[r0 + col] = lp0;
        *(uint32_t*)&oh[r1 + col] = hp1;
        *(uint32_t*)&ol[r1 + col] = lp1;
    }
}

// ===================== host =====================
static inline void transp(const float* W, __nv_bfloat16* th, __nv_bfloat16* tl, int K, int N) {
    transpose_split_kernel<<<dim3(N / 32, K / 32), dim3(32, 8)>>>(W, th, tl, K, N);
}

extern "C" void kernel_launch(void* const* d_in, const int* in_sizes, int n_in,
                              void* d_out, int out_size)
{
    const float* x      = (const float*)d_in[0];
    const float* wq     = (const float*)d_in[1];
    const float* bq     = (const float*)d_in[2];
    const float* wk     = (const float*)d_in[3];
    const float* bk     = (const float*)d_in[4];
    const float* wv     = (const float*)d_in[5];
    const float* bv     = (const float*)d_in[6];
    const float* wo     = (const float*)d_in[7];
    const float* bo     = (const float*)d_in[8];
    const float* ln1_w  = (const float*)d_in[9];
    const float* ln1_b  = (const float*)d_in[10];
    const float* ln2_w  = (const float*)d_in[11];
    const float* ln2_b  = (const float*)d_in[12];
    const float* fc1_w  = (const float*)d_in[13];
    const float* fc1_b  = (const float*)d_in[14];
    const float* fc2_w  = (const float*)d_in[15];
    const float* fc2_b  = (const float*)d_in[16];
    const float* wout   = (const float*)d_in[17];
    const float* bout   = (const float*)d_in[18];
    const float* lnout_w= (const float*)d_in[19];
    const float* lnout_b= (const float*)d_in[20];
    float* out = (float*)d_out;

    float *raw, *h2;
    __nv_bfloat16 *ah, *al, *wth, *wtl, *q_h, *q_l, *k_h, *k_l, *v_h, *v_l, *o_h, *o_l;
    cudaGetSymbolAddress((void**)&raw, g_raw);
    cudaGetSymbolAddress((void**)&h2,  g_h2);
    cudaGetSymbolAddress((void**)&ah,  g_ah);
    cudaGetSymbolAddress((void**)&al,  g_al);
    cudaGetSymbolAddress((void**)&wth, g_wth);
    cudaGetSymbolAddress((void**)&wtl, g_wtl);
    cudaGetSymbolAddress((void**)&q_h, g_qh);  cudaGetSymbolAddress((void**)&q_l, g_ql);
    cudaGetSymbolAddress((void**)&k_h, g_kh);  cudaGetSymbolAddress((void**)&k_l, g_kl);
    cudaGetSymbolAddress((void**)&v_h, g_vh);  cudaGetSymbolAddress((void**)&v_l, g_vl);
    cudaGetSymbolAddress((void**)&o_h, g_oh);  cudaGetSymbolAddress((void**)&o_l, g_ol);

    cudaFuncSetAttribute(gemm_wmma_kernel,
                         cudaFuncAttributeMaxDynamicSharedMemorySize, GEMM_SMEM);

    dim3 blk(256);
    dim3 gc(CDIM/128, ROWS/128);   // (8, 32)
    dim3 gf(FF/128,   ROWS/128);   // (32, 32)
    const int nepi_c = ROWS*CDIM/1024;
    const int nepi_f = ROWS*FF/1024;

    // 1. LN1 -> split activation
    ln_split_kernel<<<ROWS, blk>>>(x, ln1_w, ln1_b, ah, al);
    // 2-4. QKV projections -> split bf16 q,k,v
    transp(wq, wth, wtl, CDIM, CDIM);
    gemm_wmma_kernel<<<gc, blk, GEMM_SMEM>>>(ah, al, wth, wtl, raw, ROWS, CDIM, CDIM);
    epi_split_kernel<false,false><<<nepi_c, blk>>>(raw, bq, nullptr, q_h, q_l, CDIM-1);
    transp(wk, wth, wtl, CDIM, CDIM);
    gemm_wmma_kernel<<<gc, blk, GEMM_SMEM>>>(ah, al, wth, wtl, raw, ROWS, CDIM, CDIM);
    epi_split_kernel<false,false><<<nepi_c, blk>>>(raw, bk, nullptr, k_h, k_l, CDIM-1);
    transp(wv, wth, wtl, CDIM, CDIM);
    gemm_wmma_kernel<<<gc, blk, GEMM_SMEM>>>(ah, al, wth, wtl, raw, ROWS, CDIM, CDIM);
    epi_split_kernel<false,false><<<nepi_c, blk>>>(raw, bv, nullptr, v_h, v_l, CDIM-1);
    // 5. attention (tensor cores) -> split bf16 O
    attn_mma_kernel<<<dim3(SEQ/64, BATCH*HEADS), 128>>>(q_h, q_l, k_h, k_l, v_h, v_l, o_h, o_l);
    // 6. h2 = O @ wo + bo + x (fp32, residual trunk)
    transp(wo, wth, wtl, CDIM, CDIM);
    gemm_wmma_kernel<<<gc, blk, GEMM_SMEM>>>(o_h, o_l, wth, wtl, raw, ROWS, CDIM, CDIM);
    epi_plain_kernel<true><<<nepi_c, blk>>>(raw, bo, x, h2, CDIM-1);
    // 7. LN2 -> split activation
    ln_split_kernel<<<ROWS, blk>>>(h2, ln2_w, ln2_b, ah, al);
    // 8. f1 = gelu(h3 @ fc1_w + fc1_b) -> split (reuse ah/al, FF-wide)
    transp(fc1_w, wth, wtl, CDIM, FF);
    gemm_wmma_kernel<<<gf, blk, GEMM_SMEM>>>(ah, al, wth, wtl, raw, ROWS, FF, CDIM);
    epi_split_kernel<true,false><<<nepi_f, blk>>>(raw, fc1_b, nullptr, ah, al, FF-1);
    // 9. h4 = f1 @ fc2_w + fc2_b + h2 -> split (reuse ah/al, CDIM-wide)
    transp(fc2_w, wth, wtl, FF, CDIM);
    gemm_wmma_kernel<<<gc, blk, GEMM_SMEM>>>(ah, al, wth, wtl, raw, ROWS, CDIM, FF);
    epi_split_kernel<false,true><<<nepi_c, blk>>>(raw, fc2_b, h2, ah, al, CDIM-1);
    // 10. h5 = h4 @ wout + bout (fp32, reuse h2)
    transp(wout, wth, wtl, CDIM, CDIM);
    gemm_wmma_kernel<<<gc, blk, GEMM_SMEM>>>(ah, al, wth, wtl, raw, ROWS, CDIM, CDIM);
    epi_plain_kernel<false><<<nepi_c, blk>>>(raw, bout, nullptr, h2, CDIM-1);
    // 11. out = LN(h5)
    ln_kernel<<<ROWS, blk>>>(h2, lnout_w, lnout_b, out);
}